// round 3
// baseline (speedup 1.0000x reference)
#include <cuda_runtime.h>

// gain[d] = sum_n cos(n*omega*dt - fe[n,d]*(1+0.1*dw[n])*dt),  omega=1, dt=0.01
// y[b,s,d] = x[b,s,d] * gain[d]

#define MAX_D 8192
__device__ float g_gain[MAX_D];

__global__ void gain_kernel(const float* __restrict__ fe,
                            const float* __restrict__ dw,
                            int M, int D) {
    int d = blockIdx.x * blockDim.x + threadIdx.x;
    if (d >= D) return;
    const float dt = 0.01f;
    float s = 0.0f;
    #pragma unroll 16
    for (int n = 0; n < M; n++) {
        float eps = fe[n * D + d] * (1.0f + 0.1f * dw[n]);
        s += cosf((float)n * dt - eps * dt);
    }
    g_gain[d] = s;
}

// Grid-stride streaming kernel: D assumed power-of-two (4096 here).
__global__ void __launch_bounds__(256) scale_kernel(const float4* __restrict__ x,
                                                    float4* __restrict__ out,
                                                    int n4, unsigned d4mask) {
    int stride = gridDim.x * blockDim.x;
    for (int i = blockIdx.x * blockDim.x + threadIdx.x; i < n4; i += stride) {
        unsigned d4 = (unsigned)i & d4mask;
        float4 g = *reinterpret_cast<const float4*>(&g_gain[d4 * 4]);
        float4 v = x[i];
        v.x *= g.x; v.y *= g.y; v.z *= g.z; v.w *= g.w;
        out[i] = v;
    }
}

// Fallback for non-power-of-two D
__global__ void __launch_bounds__(256) scale_kernel_mod(const float4* __restrict__ x,
                                                        float4* __restrict__ out,
                                                        int n4, int d4) {
    int stride = gridDim.x * blockDim.x;
    for (int i = blockIdx.x * blockDim.x + threadIdx.x; i < n4; i += stride) {
        int r = i % d4;
        float4 g = *reinterpret_cast<const float4*>(&g_gain[r * 4]);
        float4 v = x[i];
        v.x *= g.x; v.y *= g.y; v.z *= g.z; v.w *= g.w;
        out[i] = v;
    }
}

extern "C" void kernel_launch(void* const* d_in, const int* in_sizes, int n_in,
                              void* d_out, int out_size) {
    const float* x  = (const float*)d_in[0];   // [B, S, D]
    const float* fe = (const float*)d_in[1];   // [M, D]
    const float* dw = (const float*)d_in[2];   // [M]
    // d_in[3] = coupling_matrix, unused by the reference forward.

    int M = in_sizes[2];
    int D = in_sizes[1] / M;
    int total = out_size;          // B*S*D elements
    int n4 = total / 4;            // D divisible by 4 (D=4096)

    // 1. Precompute per-dim gain (tiny)
    {
        int threads = 256;
        int blocks = (D + threads - 1) / threads;
        gain_kernel<<<blocks, threads>>>(fe, dw, M, D);
    }

    // 2. Stream x -> out with per-dim gain (HBM-bound), fixed grid + grid-stride
    {
        int threads = 256;
        int blocks = 148 * 8;      // full-chip occupancy, balanced waves
        int need = (n4 + threads - 1) / threads;
        if (blocks > need) blocks = need;
        int d4 = D / 4;
        if ((d4 & (d4 - 1)) == 0) {
            scale_kernel<<<blocks, threads>>>((const float4*)x, (float4*)d_out,
                                              n4, (unsigned)(d4 - 1));
        } else {
            scale_kernel_mod<<<blocks, threads>>>((const float4*)x, (float4*)d_out,
                                                  n4, d4);
        }
    }
}